// round 12
// baseline (speedup 1.0000x reference)
#include <cuda_runtime.h>

namespace {
constexpr int kB = 2, kNP = 4, kN = 64, kP = 24, kCin = 16, kC = 32, kT = 96;
constexpr long long kAttElems = (long long)kB * kN * kN * kT * kC;       // 25165824
constexpr int kPad = 36;          // hs row stride (floats), 16B-aligned
constexpr int kXPad = 20;         // x-tile row stride (floats), 16B-aligned
constexpr float kLog2e = 1.4426950408889634f;
}

__device__ __forceinline__ float ex2f(float x) {
    float r; asm("ex2.approx.f32 %0, %1;" : "=f"(r) : "f"(x)); return r;
}
__device__ __forceinline__ float rcpf(float x) {
    float r; asm("rcp.approx.f32 %0, %1;" : "=f"(r) : "f"(x)); return r;
}

// Fused kernel. Block = (b,s,p) x 16 i's (grid 192x4). Warp w handles
// i = i0+w and i = i0+w+8 with two sequential R8 main loops over one staged
// h-tile, halving the per-(b,s,p) prologue redundancy vs grid 192x8.
__global__ void __launch_bounds__(256, 6)
att_kernel(const float* __restrict__ x, const float* __restrict__ adj,
           const float* __restrict__ W, float* __restrict__ out) {
    __shared__ float  Ws[kCin * kC];       // W copy (512 floats)
    __shared__ float  xs[kN * kXPad];      // x rows (b,s,j,p,:), j=0..63
    __shared__ float  xf[16 * kXPad];      // x rows (b,sh,i,ph,:), 16 i's
    __shared__ float  hs[kN * kPad];       // h tile rows
    __shared__ float  hf[16 * kPad];       // h_flat rows for the 16 i's
    __shared__ float2 as2[16 * kN];        // (0.6*a, 0.4*a), a = adj*log2e

    const int tid  = threadIdx.x;
    const int warp = tid >> 5;
    const int lane = tid & 31;
    const int lg   = lane & 7;         // channel group: c = 4*lg..4*lg+3
    const int grp  = lane >> 3;        // j subgroup within warp (0..3)

    const int p  = blockIdx.x % kP;
    const int bs = blockIdx.x / kP;
    const int s  = bs & 3;
    const int b  = bs >> 2;
    const int i0 = (int)blockIdx.y * 16;

    const int t  = p * kNP + s;
    const int sh = t / kP, ph = t % kP;    // h_flat decomposition of t

    // ---- Stage: W, x-tile, xf rows, adj ----
    if (tid < 128)   // W copy: 128 float4
        *(float4*)(Ws + tid * 4) = __ldg((const float4*)W + tid);

    {   // x rows for all 64 j at (b,s,p): 256 float4
        const int j = tid >> 2, q = tid & 3;
        const float* src = x + (((b * 4 + s) * 1536) + j * 24 + p) * 16 + q * 4;
        *(float4*)(xs + j * kXPad + q * 4) = __ldg((const float4*)src);
    }
    if (tid < 64) {  // x rows for h_flat: 16 rows x 4 quads
        const int r = tid >> 2, q = tid & 3;
        const float* src = x + (((b * 4 + sh) * 1536) + (i0 + r) * 24 + ph) * 16 + q * 4;
        *(float4*)(xf + r * kXPad + q * 4) = __ldg((const float4*)src);
    }
#pragma unroll
    for (int r = 0; r < 4; ++r) {   // adj for 16 i's, pre-scaled
        int idx = tid + r * 256;
        float a = __ldg(adj + (i0 + (idx >> 6)) * kN + (idx & 63)) * kLog2e;
        as2[idx] = make_float2(0.6f * a, 0.4f * a);
    }
    __syncthreads();

    // ---- Compute h tile: thread does rows j and j+32 for channel quad q ----
    {
        const int q = tid & 7, j = tid >> 3;     // j in [0,32)
        float4 acc0 = make_float4(0.f, 0.f, 0.f, 0.f);
        float4 acc1 = make_float4(0.f, 0.f, 0.f, 0.f);
        const float* x0 = xs + j * kXPad;
        const float* x1 = xs + (j + 32) * kXPad;
#pragma unroll
        for (int k = 0; k < kCin; ++k) {
            const float4 w4 = *(const float4*)(Ws + k * kC + q * 4);
            const float a = x0[k], c = x1[k];
            acc0.x = fmaf(a, w4.x, acc0.x); acc0.y = fmaf(a, w4.y, acc0.y);
            acc0.z = fmaf(a, w4.z, acc0.z); acc0.w = fmaf(a, w4.w, acc0.w);
            acc1.x = fmaf(c, w4.x, acc1.x); acc1.y = fmaf(c, w4.y, acc1.y);
            acc1.z = fmaf(c, w4.z, acc1.z); acc1.w = fmaf(c, w4.w, acc1.w);
        }
        *(float4*)(hs + j * kPad + q * 4) = acc0;
        *(float4*)(hs + (j + 32) * kPad + q * 4) = acc1;
    }
    // ---- Compute h_flat values: thread = (i_local, c), 2 rows per thread ----
#pragma unroll
    for (int r = 0; r < 2; ++r) {
        const int il = (tid >> 5) + r * 8, c = tid & 31;
        const float* xr = xf + il * kXPad;
        float acc = 0.f;
#pragma unroll
        for (int k = 0; k < kCin; ++k)
            acc = fmaf(xr[k], Ws[k * kC + c], acc);
        hf[il * kPad + c] = acc;
    }
    __syncthreads();

    // ---- Two R8 main loops: i = i0+warp and i0+warp+8 ----
#pragma unroll
    for (int half = 0; half < 2; ++half) {
        const int il = warp + half * 8;        // i_local in [0,16)
        const int i  = i0 + il;
        const float4 hiv = *(const float4*)(hs + i * kPad + lg * 4);

        float* dstb = out + (((long long)(b * kN + i) * kN + grp) * kT + t) * kC + lg * 4;
        const float*  hrb = hs + grp * kPad + lg * 4;
        const float2* awb = as2 + il * kN + grp;

        float rs0 = 0.f, rs1 = 0.f, rs2 = 0.f, rs3 = 0.f;
#pragma unroll
        for (int jg = 0; jg < 16; ++jg) {
            const float4 hj = *(const float4*)(hrb + jg * (4 * kPad));
            const float2 A = awb[jg * 4];

            float x0 = hiv.x * hj.x, x1 = hiv.y * hj.y;
            float x2 = hiv.z * hj.z, x3 = hiv.w * hj.w;
            float e0 = ex2f(fmaf(A.x, x0, A.y * fabsf(x0)));
            float e1 = ex2f(fmaf(A.x, x1, A.y * fabsf(x1)));
            float e2 = ex2f(fmaf(A.x, x2, A.y * fabsf(x2)));
            float e3 = ex2f(fmaf(A.x, x3, A.y * fabsf(x3)));

            float sl = (e0 + e1) + (e2 + e3);
            sl += __shfl_xor_sync(0xffffffffu, sl, 1);
            sl += __shfl_xor_sync(0xffffffffu, sl, 2);
            sl += __shfl_xor_sync(0xffffffffu, sl, 4);
            const float inv = rcpf(sl);

            float o0 = e0 * inv, o1 = e1 * inv, o2 = e2 * inv, o3 = e3 * inv;
            rs0 += o0; rs1 += o1; rs2 += o2; rs3 += o3;
            *(float4*)(dstb + jg * (4 * kT * kC)) = make_float4(o0, o1, o2, o3);
        }

        // Reduce rsum across the 4 j-subgroups (lane bits 3,4)
        rs0 += __shfl_xor_sync(0xffffffffu, rs0, 8);
        rs1 += __shfl_xor_sync(0xffffffffu, rs1, 8);
        rs2 += __shfl_xor_sync(0xffffffffu, rs2, 8);
        rs3 += __shfl_xor_sync(0xffffffffu, rs3, 8);
        rs0 += __shfl_xor_sync(0xffffffffu, rs0, 16);
        rs1 += __shfl_xor_sync(0xffffffffu, rs1, 16);
        rs2 += __shfl_xor_sync(0xffffffffu, rs2, 16);
        rs3 += __shfl_xor_sync(0xffffffffu, rs3, 16);

        if (grp == 0) {   // lanes 0..7 hold full sums for channels 4*lg..4*lg+3
            const float4 hv = *(const float4*)(hf + il * kPad + lg * 4);
            float h0 = rs0 * hv.x, h1 = rs1 * hv.y;
            float h2 = rs2 * hv.z, h3 = rs3 * hv.w;
            float4 r;
            r.x = h0 > 0.f ? h0 : expm1f(h0);
            r.y = h1 > 0.f ? h1 : expm1f(h1);
            r.z = h2 > 0.f ? h2 : expm1f(h2);
            r.w = h3 > 0.f ? h3 : expm1f(h3);
            *(float4*)(out + kAttElems +
                       ((long long)(b * kN + i) * kT + t) * kC + lg * 4) = r;
        }
    }
}

extern "C" void kernel_launch(void* const* d_in, const int* in_sizes, int n_in,
                              void* d_out, int out_size) {
    const float* x   = (const float*)d_in[0];
    const float* adj = (const float*)d_in[1];
    const float* W   = (const float*)d_in[2];
    float* out = (float*)d_out;

    dim3 grid(kB * kNP * kP, kN / 16);   // (192, 4)
    att_kernel<<<grid, 256>>>(x, adj, W, out);
}